// round 15
// baseline (speedup 1.0000x reference)
#include <cuda_runtime.h>
#include <stdint.h>

#define NB 32
#define IMG_H 1024
#define IMG_W 1024
#define NPIX (IMG_H * IMG_W)
#define NOFF 16
#define NPART 32           // min/max partial blocks per image
#define TILE_R 32          // rows per fused block
#define SROWS (TILE_R + 7) // + halo rows for dr up to 7
#define NTILE (IMG_H / TILE_R)

// Scratch (static device globals — no dynamic allocation)
__device__ float               g_pmn[NB * NPART];
__device__ float               g_pmx[NB * NPART];
__device__ unsigned long long  g_sums[NB * NOFF];
__device__ unsigned int        g_done;

// Offset tables (order: for d in {1,3,5,7}, angle {0,45,90,135}: (dr, dc))
#define DR_TAB {0,1,1,1, 0,2,3,2, 0,4,5,4, 0,5,7,5}
#define DC_TAB {1,1,0,-1, 3,2,0,-2, 5,4,0,-4, 7,5,0,-5}

// ---------------------------------------------------------------------------
// Pass 1: per-image min/max partials (one partial per block, no atomics).
// Also zeroes g_sums / g_done.
// ---------------------------------------------------------------------------
__global__ void __launch_bounds__(256) k_minmax(const float* __restrict__ x) {
    int b = blockIdx.x, y = blockIdx.y;
    int tid = threadIdx.x;
    const float4* xb = (const float4*)(x + (size_t)b * NPIX);

    if (y == 0 && tid < NOFF) g_sums[b * NOFF + tid] = 0ull;
    if (b == 0 && y == 0 && tid == 0) g_done = 0u;

    float mn = 3.402823466e38f, mx = -3.402823466e38f;
    int idx = y * 256 + tid;
    int stride = NPART * 256;
#pragma unroll 8
    for (int i = idx; i < NPIX / 4; i += stride) {
        float4 v = xb[i];
        mn = fminf(mn, fminf(fminf(v.x, v.y), fminf(v.z, v.w)));
        mx = fmaxf(mx, fmaxf(fmaxf(v.x, v.y), fmaxf(v.z, v.w)));
    }
#pragma unroll
    for (int o = 16; o; o >>= 1) {
        mn = fminf(mn, __shfl_down_sync(0xffffffffu, mn, o));
        mx = fmaxf(mx, __shfl_down_sync(0xffffffffu, mx, o));
    }
    __shared__ float smn[8], smx[8];
    int warp = tid >> 5;
    if ((tid & 31) == 0) { smn[warp] = mn; smx[warp] = mx; }
    __syncthreads();
    if (tid == 0) {
        float a = smn[0], c = smx[0];
#pragma unroll
        for (int w = 1; w < 8; w++) { a = fminf(a, smn[w]); c = fmaxf(c, smx[w]); }
        g_pmn[b * NPART + y] = a;
        g_pmx[b * NPART + y] = c;
    }
}

// ---------------------------------------------------------------------------
// Pass 2: fused quantize (to smem) + SSD + final reduce (last block).
// Window W.u[12] covers image bytes [c-16, c+32). Column (c+j) -> byte (16+j).
// Only the words EXTW actually reads are loaded per neighbor row.
// ---------------------------------------------------------------------------
#define EXTW(sb) ( ((sb) & 3) ? __funnelshift_r(W.u[(sb) >> 2], W.u[((sb) >> 2) + 1], ((sb) & 3) * 8) \
                              : W.u[(sb) >> 2] )
#define ACC1(o, gg, dc) { unsigned int _n = EXTW(16 + 4*(gg) + (dc)); \
                          unsigned int _d = __vabsdiffu4(S[gg], _n); \
                          acc[o] = __dp4a(_d, _d, acc[o]); }
#define ACC4(o, dc) { ACC1(o, 0, dc) ACC1(o, 1, dc) ACC1(o, 2, dc) ACC1(o, 3, dc) }

__global__ void __launch_bounds__(256, 5) k_fused(const float* __restrict__ x,
                                                  float* __restrict__ out) {
    __shared__ __align__(16) unsigned int sq[SROWS * 256];  // 39 KB quantized tile
    __shared__ unsigned int part[8][NOFF];
    __shared__ bool last;

    int b  = blockIdx.y;
    int r0 = blockIdx.x << 5;      // first source row of this tile
    int tid = threadIdx.x;

    // Reduce the min/max partials (uniform across block; broadcast loads)
    float mn = g_pmn[b * NPART], mx = g_pmx[b * NPART];
#pragma unroll
    for (int i = 1; i < NPART; i++) {
        mn = fminf(mn, g_pmn[b * NPART + i]);
        mx = fmaxf(mx, g_pmx[b * NPART + i]);
    }
    float scale = 255.0f / (mx - mn);
    float bias  = -mn * scale;

    // --- Quantize tile rows r0 .. r0+38 into smem (row k -> sq[k*256 ..]) ---
    const float4* xb = (const float4*)x + ((size_t)b << 18);  // 2^18 float4 / image
#pragma unroll 4
    for (int k = 0; k < SROWS; k++) {
        int gr = r0 + k;
        unsigned int w = 0;
        if (gr < IMG_H) {
            float4 v = xb[gr * 256 + tid];
            int q0 = min((int)fmaf(v.x, scale, bias), 255);
            int q1 = min((int)fmaf(v.y, scale, bias), 255);
            int q2 = min((int)fmaf(v.z, scale, bias), 255);
            int q3 = min((int)fmaf(v.w, scale, bias), 255);
            w = (unsigned)q0 | ((unsigned)q1 << 8) | ((unsigned)q2 << 16) | ((unsigned)q3 << 24);
        }
        sq[k * 256 + tid] = w;
    }
    __syncthreads();

    unsigned int acc[NOFF];
#pragma unroll
    for (int o = 0; o < NOFF; o++) acc[o] = 0;

    // --- Interior fast path: 32 rows x 62 groups, 8 slots per thread ---
    for (int k = 0; k < 8; k++) {
        int slot = tid + (k << 8);
        int ri = slot >> 6;            // row in tile 0..31
        int lg = slot & 63;            // group-1: valid 0..61 -> g=1..62
        int g = lg + 1;
        if (lg < 62 && (r0 + ri) < 1016) {
            // Word pointer to S start (window word u[4])
            const unsigned int* Pw = sq + ri * 256 + g * 4;
            union { uint4 v4; uint2 d2; unsigned int u[12]; } W;
            unsigned int S[4];

            // dr = 0 : dc = 1,3,5,7  (needs u4..u9)
            { uint4 t = *(const uint4*)Pw;
              W.u[4] = t.x; W.u[5] = t.y; W.u[6] = t.z; W.u[7] = t.w;
              uint2 t2 = *(const uint2*)(Pw + 4);
              W.u[8] = t2.x; W.u[9] = t2.y; }
            S[0] = W.u[4]; S[1] = W.u[5]; S[2] = W.u[6]; S[3] = W.u[7];
            ACC4(0, 1)  ACC4(4, 3)  ACC4(8, 5)  ACC4(12, 7)

            { // dr = 1 : dc = -1,0,1  (needs u3..u8)
              const unsigned int* rp = Pw + 256;
              W.u[3] = rp[-1];
              uint4 t = *(const uint4*)rp;
              W.u[4] = t.x; W.u[5] = t.y; W.u[6] = t.z; W.u[7] = t.w;
              W.u[8] = rp[4];
              ACC4(1, 1)  ACC4(2, 0)  ACC4(3, -1) }
            { // dr = 2 : dc = -2,2   (needs u3..u8)
              const unsigned int* rp = Pw + 512;
              W.u[3] = rp[-1];
              uint4 t = *(const uint4*)rp;
              W.u[4] = t.x; W.u[5] = t.y; W.u[6] = t.z; W.u[7] = t.w;
              W.u[8] = rp[4];
              ACC4(5, 2)  ACC4(7, -2) }
            { // dr = 3 : dc = 0      (needs u4..u7)
              const unsigned int* rp = Pw + 768;
              uint4 t = *(const uint4*)rp;
              W.u[4] = t.x; W.u[5] = t.y; W.u[6] = t.z; W.u[7] = t.w;
              ACC4(6, 0) }
            { // dr = 4 : dc = -4,4   (needs u3..u8)
              const unsigned int* rp = Pw + 1024;
              W.u[3] = rp[-1];
              uint4 t = *(const uint4*)rp;
              W.u[4] = t.x; W.u[5] = t.y; W.u[6] = t.z; W.u[7] = t.w;
              W.u[8] = rp[4];
              ACC4(9, 4)  ACC4(11, -4) }
            { // dr = 5 : dc = -5,0,5 (needs u2..u9)
              const unsigned int* rp = Pw + 1280;
              uint2 a = *(const uint2*)(rp - 2);
              W.u[2] = a.x; W.u[3] = a.y;
              uint4 t = *(const uint4*)rp;
              W.u[4] = t.x; W.u[5] = t.y; W.u[6] = t.z; W.u[7] = t.w;
              uint2 c2 = *(const uint2*)(rp + 4);
              W.u[8] = c2.x; W.u[9] = c2.y;
              ACC4(10, 0) ACC4(13, 5) ACC4(15, -5) }
            { // dr = 7 : dc = 0      (needs u4..u7)
              const unsigned int* rp = Pw + 1792;
              uint4 t = *(const uint4*)rp;
              W.u[4] = t.x; W.u[5] = t.y; W.u[6] = t.z; W.u[7] = t.w;
              ACC4(14, 0) }
        }
    }

    // --- Side-column borders of this tile (c<16 or c>=1008), rows < 1016 ---
    {
        const uint8_t* sb = (const uint8_t*)sq;
        const int DR[NOFF] = DR_TAB;
        const int DC[NOFF] = DC_TAB;
#pragma unroll 1
        for (int idx = tid; idx < TILE_R * 32; idx += 256) {
            int r_in = idx >> 5;
            int cc = idx & 31;
            int c = (cc < 16) ? cc : cc + 992;
            if ((r0 + r_in) < 1016) {
                int a = sb[r_in * IMG_W + c];
#pragma unroll
                for (int o = 0; o < NOFF; o++) {
                    int c2 = c + DC[o];
                    if (c2 >= 0 && c2 < IMG_W) {       // rr <= 1022 < 1024 always
                        int d = a - (int)sb[(r_in + DR[o]) * IMG_W + c2];
                        acc[o] += (unsigned)(d * d);
                    }
                }
            }
        }
        // --- Bottom rows 1016..1023, full width (last tile only) ---
        if (r0 == 992) {
#pragma unroll 1
            for (int idx = tid; idx < 8 * IMG_W; idx += 256) {
                int r_in = 24 + (idx >> 10);           // rows 1016..1023
                int c = idx & 1023;
                int gr = r0 + r_in;
                int a = sb[r_in * IMG_W + c];
#pragma unroll
                for (int o = 0; o < NOFF; o++) {
                    int rr = gr + DR[o];
                    int c2 = c + DC[o];
                    if (rr < IMG_H && c2 >= 0 && c2 < IMG_W) {
                        int d = a - (int)sb[(r_in + DR[o]) * IMG_W + c2];
                        acc[o] += (unsigned)(d * d);
                    }
                }
            }
        }
    }

    // --- Block reduce + global accumulate ---
#pragma unroll
    for (int o = 0; o < NOFF; o++)
        acc[o] = __reduce_add_sync(0xffffffffu, acc[o]);

    int warp = tid >> 5, lane = tid & 31;
    if (lane == 0) {
#pragma unroll
        for (int o = 0; o < NOFF; o++) part[warp][o] = acc[o];
    }
    __syncthreads();
    if (tid < NOFF) {
        unsigned long long s = 0;
#pragma unroll
        for (int w = 0; w < 8; w++) s += part[w][tid];
        atomicAdd(&g_sums[b * NOFF + tid], s);
    }

    // --- Last block finalizes the output (replaces k_final launch) ---
    __syncthreads();
    if (tid == 0) {
        __threadfence();
        unsigned int old = atomicAdd(&g_done, 1u);
        last = (old == (unsigned)(NTILE * NB - 1));
    }
    __syncthreads();
    if (last) {
        const int DR[NOFF] = DR_TAB;
        const int DC[NOFF] = DC_TAB;
        for (int t = tid; t < NB * NOFF; t += 256) {
            unsigned long long sv = atomicAdd(&g_sums[t], 0ull);  // L2-coherent read
            int o = t & 15;
            int adc = DC[o] < 0 ? -DC[o] : DC[o];
            double cnt = (double)(IMG_H - DR[o]) * (double)(IMG_W - adc);
            out[t] = (float)((double)sv / cnt);
        }
    }
}

extern "C" void kernel_launch(void* const* d_in, const int* in_sizes, int n_in,
                              void* d_out, int out_size) {
    const float* x = (const float*)d_in[0];
    float* out = (float*)d_out;

    k_minmax<<<dim3(NB, NPART), 256>>>(x);
    k_fused<<<dim3(NTILE, NB), 256>>>(x, out);
}

// round 17
// speedup vs baseline: 1.1223x; 1.1223x over previous
#include <cuda_runtime.h>
#include <stdint.h>

#define NB 32
#define IMG_H 1024
#define IMG_W 1024
#define NPIX (IMG_H * IMG_W)
#define NOFF 16
#define NPART 32           // min/max partial blocks per image
#define TILE_R 32          // rows per fused block
#define SROWS (TILE_R + 7) // + halo rows for dr up to 7
#define NTILE (IMG_H / TILE_R)

// Scratch (static device globals — no dynamic allocation)
__device__ float               g_pmn[NB * NPART];
__device__ float               g_pmx[NB * NPART];
__device__ unsigned long long  g_sums[NB * NOFF];

// Offset tables (order: for d in {1,3,5,7}, angle {0,45,90,135}: (dr, dc))
#define DR_TAB {0,1,1,1, 0,2,3,2, 0,4,5,4, 0,5,7,5}
#define DC_TAB {1,1,0,-1, 3,2,0,-2, 5,4,0,-4, 7,5,0,-5}

// ---------------------------------------------------------------------------
// Pass 1: per-image min/max partials (one partial per block, no atomics).
// Also zeroes g_sums.
// ---------------------------------------------------------------------------
__global__ void __launch_bounds__(256) k_minmax(const float* __restrict__ x) {
    int b = blockIdx.x, y = blockIdx.y;
    int tid = threadIdx.x;
    const float4* xb = (const float4*)(x + (size_t)b * NPIX);

    if (y == 0 && tid < NOFF) g_sums[b * NOFF + tid] = 0ull;

    float mn = 3.402823466e38f, mx = -3.402823466e38f;
    int idx = y * 256 + tid;
    int stride = NPART * 256;
#pragma unroll 8
    for (int i = idx; i < NPIX / 4; i += stride) {
        float4 v = xb[i];
        mn = fminf(mn, fminf(fminf(v.x, v.y), fminf(v.z, v.w)));
        mx = fmaxf(mx, fmaxf(fmaxf(v.x, v.y), fmaxf(v.z, v.w)));
    }
#pragma unroll
    for (int o = 16; o; o >>= 1) {
        mn = fminf(mn, __shfl_down_sync(0xffffffffu, mn, o));
        mx = fmaxf(mx, __shfl_down_sync(0xffffffffu, mx, o));
    }
    __shared__ float smn[8], smx[8];
    int warp = tid >> 5;
    if ((tid & 31) == 0) { smn[warp] = mn; smx[warp] = mx; }
    __syncthreads();
    if (tid == 0) {
        float a = smn[0], c = smx[0];
#pragma unroll
        for (int w = 1; w < 8; w++) { a = fminf(a, smn[w]); c = fmaxf(c, smx[w]); }
        g_pmn[b * NPART + y] = a;
        g_pmx[b * NPART + y] = c;
    }
}

// ---------------------------------------------------------------------------
// Pass 2: fused quantize (to smem) + SSD (interior fast path + tile borders).
// Window W.u[12] covers tile bytes [c-16, c+32). Column (c+j) -> byte (16+j).
// ---------------------------------------------------------------------------
#define EXTW(sb) ( ((sb) & 3) ? __funnelshift_r(W.u[(sb) >> 2], W.u[((sb) >> 2) + 1], ((sb) & 3) * 8) \
                              : W.u[(sb) >> 2] )
#define ACC1(o, gg, dc) { unsigned int _n = EXTW(16 + 4*(gg) + (dc)); \
                          unsigned int _d = __vabsdiffu4(S[gg], _n); \
                          acc[o] = __dp4a(_d, _d, acc[o]); }
#define ACC4(o, dc) { ACC1(o, 0, dc) ACC1(o, 1, dc) ACC1(o, 2, dc) ACC1(o, 3, dc) }

__global__ void __launch_bounds__(256) k_fused(const float* __restrict__ x) {
    __shared__ __align__(16) unsigned int sq[SROWS * 256];  // 39 KB quantized tile
    __shared__ unsigned int part[8][NOFF];

    int b  = blockIdx.y;
    int r0 = blockIdx.x << 5;      // first source row of this tile
    int tid = threadIdx.x;

    // Reduce the min/max partials (uniform across block; broadcast loads)
    float mn = g_pmn[b * NPART], mx = g_pmx[b * NPART];
#pragma unroll
    for (int i = 1; i < NPART; i++) {
        mn = fminf(mn, g_pmn[b * NPART + i]);
        mx = fmaxf(mx, g_pmx[b * NPART + i]);
    }
    float scale = 255.0f / (mx - mn);
    float bias  = -mn * scale;

    // --- Quantize tile rows r0 .. r0+38 into smem (row k -> sq[k*256 ..]) ---
    const float4* xb = (const float4*)x + ((size_t)b << 18);  // 2^18 float4 / image
#pragma unroll
    for (int k = 0; k < SROWS; k++) {
        int gr = r0 + k;
        unsigned int w = 0;
        if (gr < IMG_H) {
            float4 v = xb[gr * 256 + tid];
            int q0 = min((int)fmaf(v.x, scale, bias), 255);
            int q1 = min((int)fmaf(v.y, scale, bias), 255);
            int q2 = min((int)fmaf(v.z, scale, bias), 255);
            int q3 = min((int)fmaf(v.w, scale, bias), 255);
            w = (unsigned)q0 | ((unsigned)q1 << 8) | ((unsigned)q2 << 16) | ((unsigned)q3 << 24);
        }
        sq[k * 256 + tid] = w;
    }
    __syncthreads();

    unsigned int acc[NOFF];
#pragma unroll
    for (int o = 0; o < NOFF; o++) acc[o] = 0;

    // --- Interior fast path: 32 rows x 62 groups, 8 slots per thread ---
    for (int k = 0; k < 8; k++) {
        int slot = tid + (k << 8);
        int ri = slot >> 6;            // row in tile 0..31
        int lg = slot & 63;            // group-1: valid 0..61 -> g=1..62
        if (lg < 62 && (r0 + ri) < 1016) {
            const uint4* P4 = (const uint4*)(sq + ri * 256) + (lg + 1);
            union { uint4 v[3]; unsigned int u[12]; } W;
            unsigned int S[4];

            // dr = 0 : dc = 1,3,5,7
            W.v[1] = P4[0];  W.v[2] = P4[1];
            S[0] = W.u[4]; S[1] = W.u[5]; S[2] = W.u[6]; S[3] = W.u[7];
            ACC4(0, 1)  ACC4(4, 3)  ACC4(8, 5)  ACC4(12, 7)
            { // dr = 1 : dc = -1,0,1
                const uint4* rp = P4 + 64;
                W.v[0] = rp[-1]; W.v[1] = rp[0]; W.v[2] = rp[1];
                ACC4(1, 1)  ACC4(2, 0)  ACC4(3, -1)
            }
            { // dr = 2 : dc = -2,2
                const uint4* rp = P4 + 128;
                W.v[0] = rp[-1]; W.v[1] = rp[0]; W.v[2] = rp[1];
                ACC4(5, 2)  ACC4(7, -2)
            }
            { // dr = 3 : dc = 0
                const uint4* rp = P4 + 192;
                W.v[1] = rp[0];
                ACC4(6, 0)
            }
            { // dr = 4 : dc = -4,4
                const uint4* rp = P4 + 256;
                W.v[0] = rp[-1]; W.v[1] = rp[0]; W.v[2] = rp[1];
                ACC4(9, 4)  ACC4(11, -4)
            }
            { // dr = 5 : dc = -5,0,5
                const uint4* rp = P4 + 320;
                W.v[0] = rp[-1]; W.v[1] = rp[0]; W.v[2] = rp[1];
                ACC4(10, 0) ACC4(13, 5) ACC4(15, -5)
            }
            { // dr = 7 : dc = 0
                const uint4* rp = P4 + 448;
                W.v[1] = rp[0];
                ACC4(14, 0)
            }
        }
    }

    // --- Side-column borders of this tile (c<16 or c>=1008), rows < 1016 ---
    {
        const uint8_t* sb = (const uint8_t*)sq;
        const int DR[NOFF] = DR_TAB;
        const int DC[NOFF] = DC_TAB;
#pragma unroll 1
        for (int idx = tid; idx < TILE_R * 32; idx += 256) {
            int r_in = idx >> 5;
            int cc = idx & 31;
            int c = (cc < 16) ? cc : cc + 992;
            if ((r0 + r_in) < 1016) {
                int a = sb[r_in * IMG_W + c];
#pragma unroll
                for (int o = 0; o < NOFF; o++) {
                    int c2 = c + DC[o];
                    if (c2 >= 0 && c2 < IMG_W) {       // rr <= 1022 < 1024 always
                        int d = a - (int)sb[(r_in + DR[o]) * IMG_W + c2];
                        acc[o] += (unsigned)(d * d);
                    }
                }
            }
        }
        // --- Bottom rows 1016..1023, full width (last tile only) ---
        if (r0 == 992) {
#pragma unroll 1
            for (int idx = tid; idx < 8 * IMG_W; idx += 256) {
                int r_in = 24 + (idx >> 10);           // rows 1016..1023
                int c = idx & 1023;
                int gr = r0 + r_in;
                int a = sb[r_in * IMG_W + c];
#pragma unroll
                for (int o = 0; o < NOFF; o++) {
                    int rr = gr + DR[o];
                    int c2 = c + DC[o];
                    if (rr < IMG_H && c2 >= 0 && c2 < IMG_W) {
                        int d = a - (int)sb[(r_in + DR[o]) * IMG_W + c2];
                        acc[o] += (unsigned)(d * d);
                    }
                }
            }
        }
    }

    // --- Block reduce + global accumulate ---
#pragma unroll
    for (int o = 0; o < NOFF; o++)
        acc[o] = __reduce_add_sync(0xffffffffu, acc[o]);

    int warp = tid >> 5, lane = tid & 31;
    if (lane == 0) {
#pragma unroll
        for (int o = 0; o < NOFF; o++) part[warp][o] = acc[o];
    }
    __syncthreads();
    if (tid < NOFF) {
        unsigned long long s = 0;
#pragma unroll
        for (int w = 0; w < 8; w++) s += part[w][tid];
        atomicAdd(&g_sums[b * NOFF + tid], s);
    }
}

// ---------------------------------------------------------------------------
__global__ void k_final(float* __restrict__ out) {
    int t = blockIdx.x * blockDim.x + threadIdx.x;
    if (t >= NB * NOFF) return;
    const int DR[NOFF] = DR_TAB;
    const int DC[NOFF] = DC_TAB;
    int o = t & 15;
    int adc = DC[o] < 0 ? -DC[o] : DC[o];
    double cnt = (double)(IMG_H - DR[o]) * (double)(IMG_W - adc);
    out[t] = (float)((double)g_sums[t] / cnt);
}

extern "C" void kernel_launch(void* const* d_in, const int* in_sizes, int n_in,
                              void* d_out, int out_size) {
    const float* x = (const float*)d_in[0];
    float* out = (float*)d_out;

    k_minmax<<<dim3(NB, NPART), 256>>>(x);
    k_fused<<<dim3(NTILE, NB), 256>>>(x);
    k_final<<<2, 256>>>(out);
}